// round 3
// baseline (speedup 1.0000x reference)
#include <cuda_runtime.h>

// ---------------------------------------------------------------------------
// Problem dims (fixed by the dataset)
// ---------------------------------------------------------------------------
constexpr int D1 = 160, H1 = 192, W1 = 224;
constexpr int N1 = D1 * H1 * W1;                 // 6,881,280
constexpr int D2 = 80, H2 = 96, W2 = 112;        // int(dim*0.5)
constexpr int N2 = D2 * H2 * W2;                 // 860,160
constexpr int D3 = 40, H3 = 48, W3 = 56;         // int(dim*0.25)
constexpr int N3 = D3 * H3 * W3;                 // 107,520

// ---------------------------------------------------------------------------
// Scratch (no cudaMalloc allowed -> __device__ globals)
// ---------------------------------------------------------------------------
__device__ float  g_bufB[5 * N1];                // WH-boxed fields (5 per scale)
__device__ float  g_z1t[N2], g_z1s[N2], g_w1[N2];
__device__ float  g_z2t[N3], g_z2s[N3], g_w2[N3];
// acc: [0]=cc_full [1]=cc_half [2]=cc_quarter [3]=sum dy^2 [4]=sum dx^2 [5]=sum dz^2
__device__ double g_acc[6];

// ---------------------------------------------------------------------------
// Reduction helpers
// ---------------------------------------------------------------------------
__device__ __forceinline__ float warpReduceSum(float v) {
#pragma unroll
    for (int o = 16; o > 0; o >>= 1) v += __shfl_down_sync(0xffffffffu, v, o);
    return v;
}

// Block-reduce v (float) then one atomicAdd(double) per block.
__device__ __forceinline__ void blockReduceAtomic(float v, double* dst) {
    __shared__ float sh[32];
    int lane = threadIdx.x & 31;
    int wid  = threadIdx.x >> 5;
    int nw   = (blockDim.x + 31) >> 5;
    __syncthreads();                  // protect sh across repeated calls
    v = warpReduceSum(v);
    if (lane == 0) sh[wid] = v;
    __syncthreads();
    if (wid == 0) {
        float t = (lane < nw) ? sh[lane] : 0.0f;
        t = warpReduceSum(t);
        if (lane == 0) atomicAdd(dst, (double)t);
    }
}

// ---------------------------------------------------------------------------
// Kernels
// ---------------------------------------------------------------------------
__global__ void init_acc_kernel() {
    if (threadIdx.x < 6) g_acc[threadIdx.x] = 0.0;
}

// gradient_loss on flow (1,3,D1,H1,W1): sums of squared finite differences
__global__ void grad_kernel(const float* __restrict__ f) {
    const int HW = H1 * W1;
    const int total = 3 * N1;
    float sdy = 0.f, sdx = 0.f, sdz = 0.f;
    for (int i = blockIdx.x * blockDim.x + threadIdx.x; i < total;
         i += gridDim.x * blockDim.x) {
        int w = i % W1;
        int r = i / W1;
        int h = r % H1;
        int d = (r / H1) % D1;
        float v = f[i];
        if (d < D1 - 1) { float t = f[i + HW] - v; sdy += t * t; }
        if (h < H1 - 1) { float t = f[i + W1] - v; sdx += t * t; }
        if (w < W1 - 1) { float t = f[i + 1]  - v; sdz += t * t; }
    }
    blockReduceAtomic(sdy, &g_acc[3]);
    blockReduceAtomic(sdx, &g_acc[4]);
    blockReduceAtomic(sdz, &g_acc[5]);
}

// ---------------------------------------------------------------------------
// Fused pass A+B: per d-slice tile, compute the 5 products (I,J,I2,J2,IJ) and
// box-sum along W then H entirely in SMEM; write the 5 fields once.
// Requirements: ROWS = HT + 2*(WW/2) == 16, WT % (256/ROWS) == 0.
// ---------------------------------------------------------------------------
template <int WW, int HT, int WT>
__global__ void boxWH_kernel(const float* __restrict__ I,
                             const float* __restrict__ J,
                             float* __restrict__ out,
                             int D, int H, int W, int N) {
    constexpr int R    = WW / 2;
    constexpr int ROWS = HT + 2 * R;         // 16 by construction
    constexpr int WTH  = WT + 2 * R;
    constexpr int CHUNKS = 256 / ROWS;       // 16
    constexpr int CW   = WT / CHUNKS;        // 4

    __shared__ float sI[ROWS][WTH + 1];
    __shared__ float sJ[ROWS][WTH + 1];
    __shared__ float s2[5][ROWS][WT + 1];

    const int d  = blockIdx.z;
    const int h0 = blockIdx.y * HT;
    const int x0 = blockIdx.x * WT;
    const int tid = threadIdx.x;

    const float* Ip = I + (long)d * H * W;
    const float* Jp = J + (long)d * H * W;

    // Load input tile (with zero padding outside the volume)
    for (int i = tid; i < ROWS * WTH; i += 256) {
        int r = i / WTH, c = i % WTH;
        int h = h0 - R + r;
        int x = x0 - R + c;
        bool ok = ((unsigned)h < (unsigned)H) && ((unsigned)x < (unsigned)W);
        sI[r][c] = ok ? Ip[h * W + x] : 0.f;
        sJ[r][c] = ok ? Jp[h * W + x] : 0.f;
    }
    __syncthreads();

    // Phase 1: W-axis box sums of the 5 products, sliding window per thread
    {
        int row   = tid % ROWS;
        int chunk = tid / ROWS;
        int xb    = chunk * CW;
        float a_s = 0.f, b_s = 0.f, aa_s = 0.f, bb_s = 0.f, ab_s = 0.f;
#pragma unroll
        for (int t = 0; t < WW; ++t) {
            float a = sI[row][xb + t];
            float b = sJ[row][xb + t];
            a_s += a; b_s += b; aa_s += a * a; bb_s += b * b; ab_s += a * b;
        }
        s2[0][row][xb] = a_s;
        s2[1][row][xb] = b_s;
        s2[2][row][xb] = aa_s;
        s2[3][row][xb] = bb_s;
        s2[4][row][xb] = ab_s;
#pragma unroll
        for (int k = 1; k < CW; ++k) {
            float a_o = sI[row][xb + k - 1];
            float b_o = sJ[row][xb + k - 1];
            float a_n = sI[row][xb + k + WW - 1];
            float b_n = sJ[row][xb + k + WW - 1];
            a_s  += a_n - a_o;
            b_s  += b_n - b_o;
            aa_s += a_n * a_n - a_o * a_o;
            bb_s += b_n * b_n - b_o * b_o;
            ab_s += a_n * b_n - a_o * b_o;
            s2[0][row][xb + k] = a_s;
            s2[1][row][xb + k] = b_s;
            s2[2][row][xb + k] = aa_s;
            s2[3][row][xb + k] = bb_s;
            s2[4][row][xb + k] = ab_s;
        }
    }
    __syncthreads();

    // Phase 2: H-axis box sums, write 5 fields to global
    for (int i = tid; i < HT * WT; i += 256) {
        int hh = i / WT, xx = i % WT;
        int h = h0 + hh, x = x0 + xx;
        if (h >= H || x >= W) continue;
        float s[5] = {0.f, 0.f, 0.f, 0.f, 0.f};
#pragma unroll
        for (int t = 0; t < WW; ++t) {
#pragma unroll
            for (int f = 0; f < 5; ++f) s[f] += s2[f][hh + t][xx];
        }
        long o = (long)(d * H + h) * W + x;
#pragma unroll
        for (int f = 0; f < 5; ++f) out[(long)f * N + o] = s[f];
    }
}

// Pass C: box-sum along D (sliding window, 5 fields) fused with NCC cc + reduce.
// grid: (x, h, nSeg)
template <int WW>
__global__ void box_d_cc_kernel(const float* __restrict__ in, double* __restrict__ acc,
                                int D, int H, int W, int N, int segD, float ws) {
    constexpr int R = WW / 2;
    int x   = blockIdx.x * blockDim.x + threadIdx.x;
    int h   = blockIdx.y;
    int seg = blockIdx.z;
    int d0 = seg * segD;
    int d1 = min(d0 + segD, D);
    bool act = (x < W) && (d0 < D);
    float win[5][WW];
    float s[5];
#pragma unroll
    for (int f = 0; f < 5; ++f) {
        s[f] = 0.f;
#pragma unroll
        for (int i = 0; i < WW; ++i) win[f][i] = 0.f;
    }
    float local = 0.f;
    float inv_ws = 1.0f / ws;
    if (act) {
        const float* base = in + h * W + x;
        for (int p = d0 - R; p < d1 + R; ++p) {
            bool vp = ((unsigned)p < (unsigned)D);
            long off = (long)p * H * W;
#pragma unroll
            for (int f = 0; f < 5; ++f) {
                float v = vp ? base[(long)f * N + off] : 0.f;
                s[f] += v - win[f][0];
#pragma unroll
                for (int i = 0; i < WW - 1; ++i) win[f][i] = win[f][i + 1];
                win[f][WW - 1] = v;
            }
            int od = p - R;
            if (od >= d0) {
                float uI = s[0] * inv_ws, uJ = s[1] * inv_ws;
                float cross = s[4] - uJ * s[0] - uI * s[1] + uI * uJ * ws;
                float Iv = s[2] - 2.f * uI * s[0] + uI * uI * ws;
                float Jv = s[3] - 2.f * uJ * s[1] + uJ * uJ * ws;
                local += cross * cross / (Iv * Jv + 1e-5f);
            }
        }
    }
    blockReduceAtomic(local, acc);
}

// resize_transform: trilinear (align_corners, clamped) downsample of tgt & src,
// values scaled by `factor`.
__global__ void downsample_kernel(const float* __restrict__ tgt,
                                  const float* __restrict__ src,
                                  float* __restrict__ zt, float* __restrict__ zs,
                                  int D, int H, int W, int Do, int Ho, int Wo,
                                  float factor) {
    int No = Do * Ho * Wo;
    int idx = blockIdx.x * blockDim.x + threadIdx.x;
    if (idx >= No) return;
    int ow = idx % Wo;
    int r  = idx / Wo;
    int oh = r % Ho;
    int od = r / Ho;
    float cd = od * ((float)(D - 1) / (float)(Do - 1));
    float ch = oh * ((float)(H - 1) / (float)(Ho - 1));
    float cw = ow * ((float)(W - 1) / (float)(Wo - 1));
    int d0 = (int)cd, h0 = (int)ch, w0 = (int)cw;
    float fd = cd - d0, fh = ch - h0, fw = cw - w0;
    int d1 = min(d0 + 1, D - 1), hh = min(h0 + 1, H - 1), w1 = min(w0 + 1, W - 1);
    d0 = min(d0, D - 1); h0 = min(h0, H - 1); w0 = min(w0, W - 1);

    float vt = 0.f, vs = 0.f;
#pragma unroll
    for (int a = 0; a < 2; ++a) {
        int di = a ? d1 : d0;
        float wd = a ? fd : 1.f - fd;
#pragma unroll
        for (int b = 0; b < 2; ++b) {
            int hi = b ? hh : h0;
            float whh = b ? fh : 1.f - fh;
#pragma unroll
            for (int c = 0; c < 2; ++c) {
                int wi = c ? w1 : w0;
                float www = c ? fw : 1.f - fw;
                float wgt = wd * whh * www;
                long o = (long)(di * H + hi) * W + wi;
                vt += wgt * tgt[o];
                vs += wgt * src[o];
            }
        }
    }
    zt[idx] = factor * vt;
    zs[idx] = factor * vs;
}

// spatial_transform: trilinear sample at grid+flow with zero padding (OOB = 0)
__global__ void warp_kernel(const float* __restrict__ src,
                            const float* __restrict__ flow,
                            float* __restrict__ out, int D, int H, int W) {
    int N = D * H * W;
    int idx = blockIdx.x * blockDim.x + threadIdx.x;
    if (idx >= N) return;
    int ow = idx % W;
    int r  = idx / W;
    int oh = r % H;
    int od = r / H;
    float cd = od + flow[idx];
    float ch = oh + flow[N + idx];
    float cw = ow + flow[2 * N + idx];
    int d0 = (int)floorf(cd), h0 = (int)floorf(ch), w0 = (int)floorf(cw);
    float fd = cd - d0, fh = ch - h0, fw = cw - w0;
    float acc = 0.f;
#pragma unroll
    for (int a = 0; a < 2; ++a) {
        int di = d0 + a;
        float wd = a ? fd : 1.f - fd;
        if ((unsigned)di >= (unsigned)D) continue;
#pragma unroll
        for (int b = 0; b < 2; ++b) {
            int hi = h0 + b;
            float whh = b ? fh : 1.f - fh;
            if ((unsigned)hi >= (unsigned)H) continue;
#pragma unroll
            for (int c = 0; c < 2; ++c) {
                int wi = w0 + c;
                float www = c ? fw : 1.f - fw;
                if ((unsigned)wi >= (unsigned)W) continue;
                acc += wd * whh * www * src[(di * H + hi) * W + wi];
            }
        }
    }
    out[idx] = acc;
}

__global__ void finalize_kernel(const float* __restrict__ h1p,
                                const float* __restrict__ h2p,
                                const float* __restrict__ h3p,
                                const float* __restrict__ h4p,
                                float* __restrict__ out) {
    double ncc = -g_acc[0] / (double)N1;
    double l1  = -g_acc[1] / (double)N2;
    double l2  = -g_acc[2] / (double)N3;
    double mdy = g_acc[3] / (3.0 * (double)(D1 - 1) * H1 * W1);
    double mdx = g_acc[4] / (3.0 * (double)D1 * (H1 - 1) * W1);
    double mdz = g_acc[5] / (3.0 * (double)D1 * H1 * (W1 - 1));
    double grad = (mdx + mdy + mdz) / 3.0;
    double loss = (double)(*h3p) * l1 + (double)(*h4p) * l2 +
                  (double)(*h1p) * ncc + (double)(*h2p) * grad;
    out[0] = (float)loss;
    out[1] = (float)ncc;
    out[2] = (float)grad;
}

// ---------------------------------------------------------------------------
// Host launch
// ---------------------------------------------------------------------------
static inline int div_up(int a, int b) { return (a + b - 1) / b; }

extern "C" void kernel_launch(void* const* d_in, const int* in_sizes, int n_in,
                              void* d_out, int out_size) {
    const float* y    = (const float*)d_in[0];
    const float* tgt  = (const float*)d_in[1];
    const float* src  = (const float*)d_in[2];
    const float* flow = (const float*)d_in[3];
    const float* if1  = (const float*)d_in[4];   // int_flow1
    const float* if2  = (const float*)d_in[6];   // int_flow2
    const float* h1   = (const float*)d_in[8];
    const float* h2   = (const float*)d_in[9];
    const float* h3   = (const float*)d_in[10];
    const float* h4   = (const float*)d_in[11];
    (void)in_sizes; (void)n_in; (void)out_size;

    float *bufB, *z1t, *z1s, *w1, *z2t, *z2s, *w2;
    double* acc;
    cudaGetSymbolAddress((void**)&bufB, g_bufB);
    cudaGetSymbolAddress((void**)&z1t, g_z1t);
    cudaGetSymbolAddress((void**)&z1s, g_z1s);
    cudaGetSymbolAddress((void**)&w1,  g_w1);
    cudaGetSymbolAddress((void**)&z2t, g_z2t);
    cudaGetSymbolAddress((void**)&z2s, g_z2s);
    cudaGetSymbolAddress((void**)&w2,  g_w2);
    cudaGetSymbolAddress((void**)&acc, g_acc);

    init_acc_kernel<<<1, 32>>>();

    // gradient loss on full-res flow
    grad_kernel<<<2048, 256>>>(flow);

    // ---------------- full-res NCC, w = 9 (HT=8, ROWS=16, WT=64) ------------
    boxWH_kernel<9, 8, 64><<<dim3(div_up(W1, 64), div_up(H1, 8), D1), 256>>>(
        tgt, y, bufB, D1, H1, W1, N1);
    box_d_cc_kernel<9><<<dim3(div_up(W1, 128), H1, 2), 128>>>(
        bufB, acc + 0, D1, H1, W1, N1, div_up(D1, 2), 729.0f);

    // ---------------- half-res NCC, w = 7 (HT=10, ROWS=16, WT=64) -----------
    downsample_kernel<<<div_up(N2, 256), 256>>>(tgt, src, z1t, z1s,
                                                D1, H1, W1, D2, H2, W2, 0.5f);
    warp_kernel<<<div_up(N2, 256), 256>>>(z1s, if1, w1, D2, H2, W2);
    boxWH_kernel<7, 10, 64><<<dim3(div_up(W2, 64), div_up(H2, 10), D2), 256>>>(
        w1, z1t, bufB, D2, H2, W2, N2);
    box_d_cc_kernel<7><<<dim3(div_up(W2, 128), H2, 2), 128>>>(
        bufB, acc + 1, D2, H2, W2, N2, div_up(D2, 2), 343.0f);

    // ---------------- quarter-res NCC, w = 5 (HT=12, ROWS=16, WT=64) --------
    downsample_kernel<<<div_up(N3, 256), 256>>>(tgt, src, z2t, z2s,
                                                D1, H1, W1, D3, H3, W3, 0.25f);
    warp_kernel<<<div_up(N3, 128), 128>>>(z2s, if2, w2, D3, H3, W3);
    boxWH_kernel<5, 12, 64><<<dim3(div_up(W3, 64), div_up(H3, 12), D3), 256>>>(
        w2, z2t, bufB, D3, H3, W3, N3);
    box_d_cc_kernel<5><<<dim3(1, H3, 4), 64>>>(
        bufB, acc + 2, D3, H3, W3, N3, div_up(D3, 4), 125.0f);

    // ---------------- combine ----------------
    finalize_kernel<<<1, 1>>>(h1, h2, h3, h4, (float*)d_out);
}

// round 10
// speedup vs baseline: 1.5244x; 1.5244x over previous
#include <cuda_runtime.h>

// ---------------------------------------------------------------------------
// Problem dims (fixed by the dataset)
// ---------------------------------------------------------------------------
constexpr int D1 = 160, H1 = 192, W1 = 224;
constexpr int N1 = D1 * H1 * W1;                 // 6,881,280
constexpr int D2 = 80, H2 = 96, W2 = 112;        // int(dim*0.5)
constexpr int N2 = D2 * H2 * W2;                 // 860,160
constexpr int D3 = 40, H3 = 48, W3 = 56;         // int(dim*0.25)
constexpr int N3 = D3 * H3 * W3;                 // 107,520

// ---------------------------------------------------------------------------
// Scratch (no cudaMalloc allowed -> __device__ globals)
// ---------------------------------------------------------------------------
__device__ float  g_bufB[5 * N1];                // WH-boxed fields (5 per scale)
__device__ float  g_z1t[N2], g_z1s[N2], g_w1[N2];
__device__ float  g_z2t[N3], g_z2s[N3], g_w2[N3];
// acc: [0]=cc_full [1]=cc_half [2]=cc_quarter [3]=sum dy^2 [4]=sum dx^2 [5]=sum dz^2
__device__ double g_acc[6];

// ---------------------------------------------------------------------------
// Helpers
// ---------------------------------------------------------------------------
__device__ __forceinline__ float4 f4add(float4 a, float4 b) {
    return make_float4(a.x + b.x, a.y + b.y, a.z + b.z, a.w + b.w);
}
__device__ __forceinline__ float4 f4sub(float4 a, float4 b) {
    return make_float4(a.x - b.x, a.y - b.y, a.z - b.z, a.w - b.w);
}
__device__ __forceinline__ float dot4(float4 t) {
    return t.x * t.x + t.y * t.y + t.z * t.z + t.w * t.w;
}

__device__ __forceinline__ float warpReduceSum(float v) {
#pragma unroll
    for (int o = 16; o > 0; o >>= 1) v += __shfl_down_sync(0xffffffffu, v, o);
    return v;
}

// Block-reduce v (float) then one atomicAdd(double) per block. Works for 2D blocks.
__device__ __forceinline__ void blockReduceAtomic(float v, double* dst) {
    __shared__ float sh[32];
    int tid  = threadIdx.y * blockDim.x + threadIdx.x;
    int nthr = blockDim.x * blockDim.y;
    int lane = tid & 31;
    int wid  = tid >> 5;
    int nw   = (nthr + 31) >> 5;
    __syncthreads();                  // protect sh across repeated calls
    v = warpReduceSum(v);
    if (lane == 0) sh[wid] = v;
    __syncthreads();
    if (wid == 0) {
        float t = (lane < nw) ? sh[lane] : 0.0f;
        t = warpReduceSum(t);
        if (lane == 0) atomicAdd(dst, (double)t);
    }
}

// ---------------------------------------------------------------------------
// Kernels
// ---------------------------------------------------------------------------
__global__ void init_acc_kernel() {
    if (threadIdx.x < 6) g_acc[threadIdx.x] = 0.0;
}

// gradient_loss on flow (1,3,D1,H1,W1): sums of squared finite differences.
// float4 version: W1 % 4 == 0 so vectors never straddle a row boundary.
__global__ void grad_kernel(const float* __restrict__ f) {
    const float4* f4 = (const float4*)f;
    constexpr int N1_4 = N1 / 4;
    constexpr int W1_4 = W1 / 4;          // 56
    constexpr int HW4  = H1 * W1 / 4;     // 10752
    const int total4 = 3 * N1_4;
    float sdy = 0.f, sdx = 0.f, sdz = 0.f;
    for (int i = blockIdx.x * blockDim.x + threadIdx.x; i < total4;
         i += gridDim.x * blockDim.x) {
        int r4 = i % N1_4;
        int w4 = r4 % W1_4;
        int rr = r4 / W1_4;
        int h  = rr % H1;
        int d  = rr / H1;
        float4 v = __ldg(f4 + i);
        if (d < D1 - 1) { float4 t = f4sub(__ldg(f4 + i + HW4), v); sdy += dot4(t); }
        if (h < H1 - 1) { float4 t = f4sub(__ldg(f4 + i + W1_4), v); sdx += dot4(t); }
        float t0 = v.y - v.x, t1 = v.z - v.y, t2 = v.w - v.z;
        sdz += t0 * t0 + t1 * t1 + t2 * t2;
        if (w4 < W1_4 - 1) {
            float nxt = __ldg(f + 4 * i + 4);
            float t3 = nxt - v.w;
            sdz += t3 * t3;
        }
    }
    blockReduceAtomic(sdy, &g_acc[3]);
    blockReduceAtomic(sdx, &g_acc[4]);
    blockReduceAtomic(sdz, &g_acc[5]);
}

// ---------------------------------------------------------------------------
// Fused pass A+B: per d-slice tile, compute the 5 products (I,J,I2,J2,IJ) and
// box-sum along W then H entirely in SMEM; write the 5 fields once.
// Requirements: ROWS = HT + 2*(WW/2) == 16, WT % (256/ROWS) == 0.
// ---------------------------------------------------------------------------
template <int WW, int HT, int WT>
__global__ void boxWH_kernel(const float* __restrict__ I,
                             const float* __restrict__ J,
                             float* __restrict__ out,
                             int D, int H, int W, int N) {
    constexpr int R    = WW / 2;
    constexpr int ROWS = HT + 2 * R;         // 16 by construction
    constexpr int WTH  = WT + 2 * R;
    constexpr int CHUNKS = 256 / ROWS;       // 16
    constexpr int CW   = WT / CHUNKS;        // 4

    __shared__ float sI[ROWS][WTH + 1];
    __shared__ float sJ[ROWS][WTH + 1];
    __shared__ float s2[5][ROWS][WT + 1];

    const int d  = blockIdx.z;
    const int h0 = blockIdx.y * HT;
    const int x0 = blockIdx.x * WT;
    const int tid = threadIdx.x;

    const float* Ip = I + (long)d * H * W;
    const float* Jp = J + (long)d * H * W;

    // Load input tile (with zero padding outside the volume)
    for (int i = tid; i < ROWS * WTH; i += 256) {
        int r = i / WTH, c = i % WTH;
        int h = h0 - R + r;
        int x = x0 - R + c;
        bool ok = ((unsigned)h < (unsigned)H) && ((unsigned)x < (unsigned)W);
        sI[r][c] = ok ? Ip[h * W + x] : 0.f;
        sJ[r][c] = ok ? Jp[h * W + x] : 0.f;
    }
    __syncthreads();

    // Phase 1: W-axis box sums of the 5 products, sliding window per thread
    {
        int row   = tid % ROWS;
        int chunk = tid / ROWS;
        int xb    = chunk * CW;
        float a_s = 0.f, b_s = 0.f, aa_s = 0.f, bb_s = 0.f, ab_s = 0.f;
#pragma unroll
        for (int t = 0; t < WW; ++t) {
            float a = sI[row][xb + t];
            float b = sJ[row][xb + t];
            a_s += a; b_s += b; aa_s += a * a; bb_s += b * b; ab_s += a * b;
        }
        s2[0][row][xb] = a_s;
        s2[1][row][xb] = b_s;
        s2[2][row][xb] = aa_s;
        s2[3][row][xb] = bb_s;
        s2[4][row][xb] = ab_s;
#pragma unroll
        for (int k = 1; k < CW; ++k) {
            float a_o = sI[row][xb + k - 1];
            float b_o = sJ[row][xb + k - 1];
            float a_n = sI[row][xb + k + WW - 1];
            float b_n = sJ[row][xb + k + WW - 1];
            a_s  += a_n - a_o;
            b_s  += b_n - b_o;
            aa_s += a_n * a_n - a_o * a_o;
            bb_s += b_n * b_n - b_o * b_o;
            ab_s += a_n * b_n - a_o * b_o;
            s2[0][row][xb + k] = a_s;
            s2[1][row][xb + k] = b_s;
            s2[2][row][xb + k] = aa_s;
            s2[3][row][xb + k] = bb_s;
            s2[4][row][xb + k] = ab_s;
        }
    }
    __syncthreads();

    // Phase 2: H-axis box sums, write 5 fields to global.
    constexpr int TPC = 256 / WT;            // threads per column (4 for WT=64)
    if constexpr ((HT % TPC) == 0) {
        // h-sliding strip per thread: init WW-row sum, then +2 rows per output
        constexpr int CNT = HT / TPC;
        int xx  = tid % WT;
        int hh0 = (tid / WT) * CNT;
        int x   = x0 + xx;
        if (x < W) {
            float s[5];
#pragma unroll
            for (int f = 0; f < 5; ++f) {
                float t = 0.f;
#pragma unroll
                for (int r = 0; r < WW; ++r) t += s2[f][hh0 + r][xx];
                s[f] = t;
            }
#pragma unroll
            for (int k = 0; k < CNT; ++k) {
                int h = h0 + hh0 + k;
                if (h < H) {
                    long o = (long)(d * H + h) * W + x;
#pragma unroll
                    for (int f = 0; f < 5; ++f) out[(long)f * N + o] = s[f];
                }
                if (k + 1 < CNT) {
#pragma unroll
                    for (int f = 0; f < 5; ++f)
                        s[f] += s2[f][hh0 + k + WW][xx] - s2[f][hh0 + k][xx];
                }
            }
        }
    } else {
        for (int i = tid; i < HT * WT; i += 256) {
            int hh = i / WT, xx = i % WT;
            int h = h0 + hh, x = x0 + xx;
            if (h >= H || x >= W) continue;
            float s[5] = {0.f, 0.f, 0.f, 0.f, 0.f};
#pragma unroll
            for (int t = 0; t < WW; ++t) {
#pragma unroll
                for (int f = 0; f < 5; ++f) s[f] += s2[f][hh + t][xx];
            }
            long o = (long)(d * H + h) * W + x;
#pragma unroll
            for (int f = 0; f < 5; ++f) out[(long)f * N + o] = s[f];
        }
    }
}

// ---------------------------------------------------------------------------
// Pass C: box-sum along D fused with NCC cc + reduce. float4 lanes.
// Running sum updated by re-loading the trailing slab (L2 hit) instead of a
// register shift window -> high MLP, vector loads, BW-bound.
// block = (lanes, rows), grid = (1, H/rows, nSeg)
// ---------------------------------------------------------------------------
#define CC_ONE(C)                                                              \
    {                                                                          \
        float a = s[0].C, b = s[1].C, aa = s[2].C, bb = s[3].C, ab = s[4].C;   \
        float uI = a * inv_ws, uJ = b * inv_ws;                                \
        float cross = ab - uJ * a - uI * b + uI * uJ * ws;                     \
        float Iv = aa - 2.f * uI * a + uI * uI * ws;                           \
        float Jv = bb - 2.f * uJ * b + uJ * uJ * ws;                           \
        local += cross * cross / (Iv * Jv + 1e-5f);                            \
    }

template <int WW>
__global__ void box_d_cc4_kernel(const float4* __restrict__ in,
                                 double* __restrict__ acc,
                                 int D, int H, int W4, int N4,
                                 int segD, float ws) {
    constexpr int R = WW / 2;
    const int x4 = threadIdx.x;
    const int h  = blockIdx.y * blockDim.y + threadIdx.y;
    const int d0 = blockIdx.z * segD;
    const int d1 = min(d0 + segD, D);
    const bool act = (x4 < W4) && (h < H);
    float local = 0.f;
    if (act) {
        const float4* base = in + (long)h * W4 + x4;
        const long slab = (long)H * W4;
        const float inv_ws = 1.0f / ws;
        float4 s[5];
#pragma unroll
        for (int f = 0; f < 5; ++f) s[f] = make_float4(0.f, 0.f, 0.f, 0.f);
        // init window for output d0: sum of valid slabs [d0-R, d0+R]
        for (int p = d0 - R; p <= d0 + R; ++p) {
            if ((unsigned)p < (unsigned)D) {
#pragma unroll
                for (int f = 0; f < 5; ++f)
                    s[f] = f4add(s[f], __ldg(base + (long)f * N4 + (long)p * slab));
            }
        }
        for (int od = d0; od < d1; ++od) {
            CC_ONE(x) CC_ONE(y) CC_ONE(z) CC_ONE(w)
            if (od + 1 < d1) {
                int pn = od + 1 + R;
                int po = od - R;
#pragma unroll
                for (int f = 0; f < 5; ++f) {
                    float4 vn = (pn < D)
                        ? __ldg(base + (long)f * N4 + (long)pn * slab)
                        : make_float4(0.f, 0.f, 0.f, 0.f);
                    float4 vo = (po >= 0)
                        ? __ldg(base + (long)f * N4 + (long)po * slab)
                        : make_float4(0.f, 0.f, 0.f, 0.f);
                    s[f] = f4add(s[f], f4sub(vn, vo));
                }
            }
        }
    }
    blockReduceAtomic(local, acc);
}

// resize_transform: trilinear (align_corners, clamped) downsample of tgt & src,
// values scaled by `factor`.
__global__ void downsample_kernel(const float* __restrict__ tgt,
                                  const float* __restrict__ src,
                                  float* __restrict__ zt, float* __restrict__ zs,
                                  int D, int H, int W, int Do, int Ho, int Wo,
                                  float factor) {
    int No = Do * Ho * Wo;
    int idx = blockIdx.x * blockDim.x + threadIdx.x;
    if (idx >= No) return;
    int ow = idx % Wo;
    int r  = idx / Wo;
    int oh = r % Ho;
    int od = r / Ho;
    float cd = od * ((float)(D - 1) / (float)(Do - 1));
    float ch = oh * ((float)(H - 1) / (float)(Ho - 1));
    float cw = ow * ((float)(W - 1) / (float)(Wo - 1));
    int d0 = (int)cd, h0 = (int)ch, w0 = (int)cw;
    float fd = cd - d0, fh = ch - h0, fw = cw - w0;
    int d1 = min(d0 + 1, D - 1), hh = min(h0 + 1, H - 1), w1 = min(w0 + 1, W - 1);
    d0 = min(d0, D - 1); h0 = min(h0, H - 1); w0 = min(w0, W - 1);

    float vt = 0.f, vs = 0.f;
#pragma unroll
    for (int a = 0; a < 2; ++a) {
        int di = a ? d1 : d0;
        float wd = a ? fd : 1.f - fd;
#pragma unroll
        for (int b = 0; b < 2; ++b) {
            int hi = b ? hh : h0;
            float whh = b ? fh : 1.f - fh;
#pragma unroll
            for (int c = 0; c < 2; ++c) {
                int wi = c ? w1 : w0;
                float www = c ? fw : 1.f - fw;
                float wgt = wd * whh * www;
                long o = (long)(di * H + hi) * W + wi;
                vt += wgt * tgt[o];
                vs += wgt * src[o];
            }
        }
    }
    zt[idx] = factor * vt;
    zs[idx] = factor * vs;
}

// spatial_transform: trilinear sample at grid+flow with zero padding (OOB = 0)
__global__ void warp_kernel(const float* __restrict__ src,
                            const float* __restrict__ flow,
                            float* __restrict__ out, int D, int H, int W) {
    int N = D * H * W;
    int idx = blockIdx.x * blockDim.x + threadIdx.x;
    if (idx >= N) return;
    int ow = idx % W;
    int r  = idx / W;
    int oh = r % H;
    int od = r / H;
    float cd = od + flow[idx];
    float ch = oh + flow[N + idx];
    float cw = ow + flow[2 * N + idx];
    int d0 = (int)floorf(cd), h0 = (int)floorf(ch), w0 = (int)floorf(cw);
    float fd = cd - d0, fh = ch - h0, fw = cw - w0;
    float acc = 0.f;
#pragma unroll
    for (int a = 0; a < 2; ++a) {
        int di = d0 + a;
        float wd = a ? fd : 1.f - fd;
        if ((unsigned)di >= (unsigned)D) continue;
#pragma unroll
        for (int b = 0; b < 2; ++b) {
            int hi = h0 + b;
            float whh = b ? fh : 1.f - fh;
            if ((unsigned)hi >= (unsigned)H) continue;
#pragma unroll
            for (int c = 0; c < 2; ++c) {
                int wi = w0 + c;
                float www = c ? fw : 1.f - fw;
                if ((unsigned)wi >= (unsigned)W) continue;
                acc += wd * whh * www * src[(di * H + hi) * W + wi];
            }
        }
    }
    out[idx] = acc;
}

__global__ void finalize_kernel(const float* __restrict__ h1p,
                                const float* __restrict__ h2p,
                                const float* __restrict__ h3p,
                                const float* __restrict__ h4p,
                                float* __restrict__ out) {
    double ncc = -g_acc[0] / (double)N1;
    double l1  = -g_acc[1] / (double)N2;
    double l2  = -g_acc[2] / (double)N3;
    double mdy = g_acc[3] / (3.0 * (double)(D1 - 1) * H1 * W1);
    double mdx = g_acc[4] / (3.0 * (double)D1 * (H1 - 1) * W1);
    double mdz = g_acc[5] / (3.0 * (double)D1 * H1 * (W1 - 1));
    double grad = (mdx + mdy + mdz) / 3.0;
    double loss = (double)(*h3p) * l1 + (double)(*h4p) * l2 +
                  (double)(*h1p) * ncc + (double)(*h2p) * grad;
    out[0] = (float)loss;
    out[1] = (float)ncc;
    out[2] = (float)grad;
}

// ---------------------------------------------------------------------------
// Host launch
// ---------------------------------------------------------------------------
static inline int div_up(int a, int b) { return (a + b - 1) / b; }

extern "C" void kernel_launch(void* const* d_in, const int* in_sizes, int n_in,
                              void* d_out, int out_size) {
    const float* y    = (const float*)d_in[0];
    const float* tgt  = (const float*)d_in[1];
    const float* src  = (const float*)d_in[2];
    const float* flow = (const float*)d_in[3];
    const float* if1  = (const float*)d_in[4];   // int_flow1
    const float* if2  = (const float*)d_in[6];   // int_flow2
    const float* h1   = (const float*)d_in[8];
    const float* h2   = (const float*)d_in[9];
    const float* h3   = (const float*)d_in[10];
    const float* h4   = (const float*)d_in[11];
    (void)in_sizes; (void)n_in; (void)out_size;

    float *bufB, *z1t, *z1s, *w1, *z2t, *z2s, *w2;
    double* acc;
    cudaGetSymbolAddress((void**)&bufB, g_bufB);
    cudaGetSymbolAddress((void**)&z1t, g_z1t);
    cudaGetSymbolAddress((void**)&z1s, g_z1s);
    cudaGetSymbolAddress((void**)&w1,  g_w1);
    cudaGetSymbolAddress((void**)&z2t, g_z2t);
    cudaGetSymbolAddress((void**)&z2s, g_z2s);
    cudaGetSymbolAddress((void**)&w2,  g_w2);
    cudaGetSymbolAddress((void**)&acc, g_acc);

    init_acc_kernel<<<1, 32>>>();

    // gradient loss on full-res flow
    grad_kernel<<<2048, 256>>>(flow);

    // ---------------- full-res NCC, w = 9 (HT=8, ROWS=16, WT=64) ------------
    boxWH_kernel<9, 8, 64><<<dim3(div_up(W1, 64), div_up(H1, 8), D1), 256>>>(
        tgt, y, bufB, D1, H1, W1, N1);
    box_d_cc4_kernel<9><<<dim3(1, H1 / 2, 8), dim3(64, 2)>>>(
        (const float4*)bufB, acc + 0, D1, H1, W1 / 4, N1 / 4, div_up(D1, 8), 729.0f);

    // ---------------- downsample both scales back-to-back (L2 reuse) --------
    downsample_kernel<<<div_up(N2, 256), 256>>>(tgt, src, z1t, z1s,
                                                D1, H1, W1, D2, H2, W2, 0.5f);
    downsample_kernel<<<div_up(N3, 256), 256>>>(tgt, src, z2t, z2s,
                                                D1, H1, W1, D3, H3, W3, 0.25f);

    // ---------------- half-res NCC, w = 7 (HT=10, ROWS=16, WT=64) -----------
    warp_kernel<<<div_up(N2, 256), 256>>>(z1s, if1, w1, D2, H2, W2);
    boxWH_kernel<7, 10, 64><<<dim3(div_up(W2, 64), div_up(H2, 10), D2), 256>>>(
        w1, z1t, bufB, D2, H2, W2, N2);
    box_d_cc4_kernel<7><<<dim3(1, H2 / 4, 8), dim3(32, 4)>>>(
        (const float4*)bufB, acc + 1, D2, H2, W2 / 4, N2 / 4, div_up(D2, 8), 343.0f);

    // ---------------- quarter-res NCC, w = 5 (HT=12, ROWS=16, WT=64) --------
    warp_kernel<<<div_up(N3, 128), 128>>>(z2s, if2, w2, D3, H3, W3);
    boxWH_kernel<5, 12, 64><<<dim3(div_up(W3, 64), div_up(H3, 12), D3), 256>>>(
        w2, z2t, bufB, D3, H3, W3, N3);
    box_d_cc4_kernel<5><<<dim3(1, H3 / 8, 5), dim3(16, 8)>>>(
        (const float4*)bufB, acc + 2, D3, H3, W3 / 4, N3 / 4, div_up(D3, 5), 125.0f);

    // ---------------- combine ----------------
    finalize_kernel<<<1, 1>>>(h1, h2, h3, h4, (float*)d_out);
}